// round 9
// baseline (speedup 1.0000x reference)
#include <cuda_runtime.h>
#include <cuda_bf16.h>
#include <cstdint>
#include <math.h>

// ---------------- problem constants ----------------
#define T_STEPS 512
#define B_SZ    64
#define D_SZ    512
#define H_SZ    1024
#define G4      4096          // 4*H
#define BH      (B_SZ*H_SZ)   // 65536
#define NCTA    128

// ---------------- global scratch / sync state ----------------
__device__ float g_xg[(size_t)T_STEPS * B_SZ * G4];   // 512 MB, Xg = X@Wx + b
__device__ __nv_bfloat16 g_Hh[2][BH];                 // H split-bf16 hi, ping-pong
__device__ __nv_bfloat16 g_Hl[2][BH];                 // H split-bf16 lo
__device__ __nv_bfloat16 g_Xh[(size_t)T_STEPS * B_SZ * D_SZ];   // X split hi
__device__ __nv_bfloat16 g_Xl[(size_t)T_STEPS * B_SZ * D_SZ];   // X split lo
__device__ __nv_bfloat16 g_Wxh[(size_t)D_SZ * G4];    // Wx concat split hi
__device__ __nv_bfloat16 g_Wxl[(size_t)D_SZ * G4];    // Wx concat split lo
__device__ float g_bcat[G4];                          // bias concat
__device__ int      g_ready[NCTA];                    // per-CTA step counter
__device__ unsigned g_arrive = 0;
__device__ unsigned g_gen    = 0;

// ---------------- helpers ----------------
__device__ __forceinline__ uint32_t smem_u32(const void* p) {
    uint32_t a;
    asm("{ .reg .u64 t; cvta.to.shared.u64 t, %1; cvt.u32.u64 %0, t; }" : "=r"(a) : "l"(p));
    return a;
}
__device__ __forceinline__ void ldsm_x4(uint32_t* r, uint32_t addr) {
    asm volatile("ldmatrix.sync.aligned.m8n8.x4.shared.b16 {%0,%1,%2,%3}, [%4];"
                 : "=r"(r[0]), "=r"(r[1]), "=r"(r[2]), "=r"(r[3]) : "r"(addr));
}
__device__ __forceinline__ void ldsm_x4t(uint32_t* r, uint32_t addr) {
    asm volatile("ldmatrix.sync.aligned.m8n8.x4.trans.shared.b16 {%0,%1,%2,%3}, [%4];"
                 : "=r"(r[0]), "=r"(r[1]), "=r"(r[2]), "=r"(r[3]) : "r"(addr));
}
__device__ __forceinline__ void mma16816(float* c, const uint32_t* a, uint32_t b0, uint32_t b1) {
    asm volatile(
        "mma.sync.aligned.m16n8k16.row.col.f32.bf16.bf16.f32 "
        "{%0,%1,%2,%3}, {%4,%5,%6,%7}, {%8,%9}, {%0,%1,%2,%3};"
        : "+f"(c[0]), "+f"(c[1]), "+f"(c[2]), "+f"(c[3])
        : "r"(a[0]), "r"(a[1]), "r"(a[2]), "r"(a[3]), "r"(b0), "r"(b1));
}
__device__ __forceinline__ void cp16(uint32_t saddr, const void* g) {
    asm volatile("cp.async.cg.shared.global [%0], [%1], 16;" :: "r"(saddr), "l"(g));
}
#define CP_COMMIT() asm volatile("cp.async.commit_group;" ::: "memory")
#define CP_WAIT(N)  asm volatile("cp.async.wait_group %0;" :: "n"(N) : "memory")

__device__ __forceinline__ void bar_named(int id, int cnt) {
    asm volatile("bar.sync %0, %1;" :: "r"(id), "r"(cnt) : "memory");
}
__device__ __forceinline__ void wait_ready(int idx, int target) {
    int v;
    do {
        asm volatile("ld.acquire.gpu.s32 %0, [%1];" : "=r"(v) : "l"(g_ready + idx) : "memory");
        if (v < target) __nanosleep(32);
    } while (v < target);
}

// self-resetting generation barrier (replay-safe)
__device__ __forceinline__ void init_barrier() {
    __syncthreads();
    if (threadIdx.x == 0) {
        __threadfence();
        unsigned gen;
        asm volatile("ld.acquire.gpu.u32 %0, [%1];" : "=r"(gen) : "l"(&g_gen) : "memory");
        unsigned old = atomicAdd(&g_arrive, 1u);
        if (old == NCTA - 1) {
            atomicExch(&g_arrive, 0u);
            __threadfence();
            atomicAdd(&g_gen, 1u);
        } else {
            unsigned cur;
            do {
                __nanosleep(64);
                asm volatile("ld.acquire.gpu.u32 %0, [%1];" : "=r"(cur) : "l"(&g_gen) : "memory");
            } while (cur == gen);
        }
        __threadfence();
    }
    __syncthreads();
}

__device__ __forceinline__ void split2u(float v, unsigned& h, unsigned& l) {
    __nv_bfloat16 hb = __float2bfloat16(v);
    float r = v - __bfloat162float(hb);
    __nv_bfloat16 lb = __float2bfloat16(r);
    h = (unsigned)*reinterpret_cast<unsigned short*>(&hb);
    l = (unsigned)*reinterpret_cast<unsigned short*>(&lb);
}

// ====================================================================
// Kernel 0: split X and Wx (concat) into bf16 hi/lo; build bias concat.
// ====================================================================
#define NX4 ((size_t)T_STEPS * B_SZ * D_SZ / 4)      // 4,194,304
#define NW4 ((size_t)D_SZ * G4 / 4)                  // 524,288

__global__ void __launch_bounds__(256) conv_prep(
    const float* __restrict__ X,
    const float* __restrict__ Wx0, const float* __restrict__ Wx1,
    const float* __restrict__ Wx2, const float* __restrict__ Wx3,
    const float* __restrict__ b0p, const float* __restrict__ b1p,
    const float* __restrict__ b2p, const float* __restrict__ b3p)
{
    size_t i = (size_t)blockIdx.x * 256 + threadIdx.x;
    if (i < NX4) {
        float4 v = ((const float4*)X)[i];
        unsigned h0, h1, h2, h3, l0, l1, l2, l3;
        split2u(v.x, h0, l0); split2u(v.y, h1, l1);
        split2u(v.z, h2, l2); split2u(v.w, h3, l3);
        *(uint2*)&g_Xh[i * 4] = make_uint2(h0 | (h1 << 16), h2 | (h3 << 16));
        *(uint2*)&g_Xl[i * 4] = make_uint2(l0 | (l1 << 16), l2 | (l3 << 16));
    } else if (i < NX4 + NW4) {
        size_t d = i - NX4;
        int k  = (int)(d >> 10);
        int c4 = (int)(d & 1023);
        int col  = c4 * 4;
        int gate = col >> 10;
        int n    = col & 1023;
        const float* W = (gate == 0) ? Wx0 : (gate == 1) ? Wx1 : (gate == 2) ? Wx2 : Wx3;
        float4 v = *(const float4*)&W[(size_t)k * 1024 + n];
        unsigned h0, h1, h2, h3, l0, l1, l2, l3;
        split2u(v.x, h0, l0); split2u(v.y, h1, l1);
        split2u(v.z, h2, l2); split2u(v.w, h3, l3);
        *(uint2*)&g_Wxh[d * 4] = make_uint2(h0 | (h1 << 16), h2 | (h3 << 16));
        *(uint2*)&g_Wxl[d * 4] = make_uint2(l0 | (l1 << 16), l2 | (l3 << 16));
    }
    if (i < G4 / 4) {
        int col = (int)i * 4;
        int gate = col >> 10, n = col & 1023;
        const float* bg = (gate == 0) ? b0p : (gate == 1) ? b1p : (gate == 2) ? b2p : b3p;
        ((float4*)g_bcat)[i] = *(const float4*)&bg[n];
    }
}

// ====================================================================
// Kernel 1: Xg = X @ Wxcat + bcat via split-bf16 3-pass mma.sync.
// (unchanged from passing R7/R8 version)
// ====================================================================
#define XA_HI(buf) ((buf)*36864)                   // [128][72] bf16
#define XA_LO(buf) ((buf)*36864 + 18432)
#define XB_HI(buf) (73728 + (buf)*34816)           // [64][136] bf16
#define XB_LO(buf) (73728 + (buf)*34816 + 17408)
#define XG_SMEM    143360

__global__ void __launch_bounds__(256, 1) xg_mma()
{
    extern __shared__ char smc[];
    const uint32_t smem_base = smem_u32(smc);
    const int tid  = threadIdx.x;
    const int wid  = tid >> 5;
    const int lane = tid & 31;
    const int m0   = blockIdx.y * 128;
    const int nb   = blockIdx.x * 128;
    const int mw   = (wid & 3) * 32;
    const int nw   = (wid >> 2) * 64;

    const int arow = ((lane >> 3) & 1) * 8 + (lane & 7);
    const int acol = (lane >> 4) * 8;
    const int brow = ((lane >> 3) & 1) * 8 + (lane & 7);
    const int bcol = (lane >> 4) * 8;

    float acc[2][8][4];
    #pragma unroll
    for (int m = 0; m < 2; ++m)
        #pragma unroll
        for (int n = 0; n < 8; ++n)
            #pragma unroll
            for (int q = 0; q < 4; ++q) acc[m][n][q] = 0.f;

    auto issue_chunk = [&](int s, int buf) {
        #pragma unroll
        for (int i = 0; i < 4; ++i) {
            int idx = tid + i * 256;
            int row = idx >> 3, c8 = (idx & 7) * 8;
            uint32_t sa = smem_base + XA_HI(buf) + (uint32_t)(row * 72 + c8) * 2u;
            size_t go = (size_t)(m0 + row) * D_SZ + s * 64 + c8;
            cp16(sa,          g_Xh + go);
            cp16(sa + 18432u, g_Xl + go);
        }
        #pragma unroll
        for (int i = 0; i < 4; ++i) {
            int idx = tid + i * 256;
            int r = idx >> 4, c8 = (idx & 15) * 8;
            uint32_t sb = smem_base + XB_HI(buf) + (uint32_t)(r * 136 + c8) * 2u;
            size_t go = (size_t)(s * 64 + r) * G4 + nb + c8;
            cp16(sb,          g_Wxh + go);
            cp16(sb + 17408u, g_Wxl + go);
        }
        CP_COMMIT();
    };

    issue_chunk(0, 0);
    #pragma unroll 1
    for (int s = 0; s < 8; ++s) {
        if (s < 7) { issue_chunk(s + 1, (s + 1) & 1); CP_WAIT(1); }
        else       { CP_WAIT(0); }
        __syncthreads();

        const int buf = s & 1;
        const uint32_t Ah = smem_base + XA_HI(buf);
        const uint32_t Bh = smem_base + XB_HI(buf);
        #pragma unroll
        for (int kt = 0; kt < 4; ++kt) {
            uint32_t ah[2][4], al[2][4];
            #pragma unroll
            for (int m = 0; m < 2; ++m) {
                uint32_t ar = Ah + (uint32_t)((mw + m * 16 + arow) * 72 + kt * 16 + acol) * 2u;
                ldsm_x4(ah[m], ar);
                ldsm_x4(al[m], ar + 18432u);
            }
            uint32_t bh[4][4], bl[4][4];
            #pragma unroll
            for (int np = 0; np < 4; ++np) {
                uint32_t br = Bh + (uint32_t)((kt * 16 + brow) * 136 + nw + np * 16 + bcol) * 2u;
                ldsm_x4t(bh[np], br);
                ldsm_x4t(bl[np], br + 17408u);
            }
            #pragma unroll
            for (int m = 0; m < 2; ++m)
                #pragma unroll
                for (int np = 0; np < 4; ++np) {
                    mma16816(acc[m][2*np],   ah[m], bh[np][0], bh[np][1]);
                    mma16816(acc[m][2*np],   ah[m], bl[np][0], bl[np][1]);
                    mma16816(acc[m][2*np],   al[m], bh[np][0], bh[np][1]);
                    mma16816(acc[m][2*np+1], ah[m], bh[np][2], bh[np][3]);
                    mma16816(acc[m][2*np+1], ah[m], bl[np][2], bl[np][3]);
                    mma16816(acc[m][2*np+1], al[m], bh[np][2], bh[np][3]);
                }
        }
        __syncthreads();
    }

    const int r0    = m0 + mw + (lane >> 2);
    const int cbase = nb + nw + (lane & 3) * 2;
    #pragma unroll
    for (int m = 0; m < 2; ++m) {
        #pragma unroll
        for (int nt = 0; nt < 8; ++nt) {
            int col = cbase + nt * 8;
            float b0 = g_bcat[col], b1 = g_bcat[col + 1];
            int rr = r0 + m * 16;
            float* p0 = g_xg + (size_t)rr * G4 + col;
            float* p1 = g_xg + (size_t)(rr + 8) * G4 + col;
            *(float2*)p0 = make_float2(acc[m][nt][0] + b0, acc[m][nt][1] + b1);
            *(float2*)p1 = make_float2(acc[m][nt][2] + b0, acc[m][nt][3] + b1);
        }
    }
}

// ====================================================================
// Kernel 2: persistent mma.sync recurrence v4 — barrier-free K-loop.
// Warp pair {mt, mt+4} owns A rows [mt*16,+16): npair0 stages hi half,
// npair1 stages lo half into a private 4-deep ring; sync via warp-local
// cp.async.wait_group + one named bar.sync(1+mt, 64) per chunk. Chunk
// consumption order rotated by CTA group so remote producers get slack.
// W resident in SMEM hi|lo interleaved (stride 72 bf16, 144B rows).
// ====================================================================

#define RW 0                          // 1024 x 144B = 147456
#define RA 147456                     // 4 mt x 4 bufs x 4608 = 73728
#define RG 221184                     // 64x33 f32 = 8448
#define RT 229632                     // total dynamic smem

__global__ void __launch_bounds__(256, 1) lstm_rec(
    const float* __restrict__ Wh0, const float* __restrict__ Wh1,
    const float* __restrict__ Wh2, const float* __restrict__ Wh3,
    float* __restrict__ out, int out_size)
{
    extern __shared__ char smc[];
    const uint32_t smem_base = smem_u32(smc);
    const int tid  = threadIdx.x;
    const int wid  = tid >> 5;
    const int lane = tid & 31;
    const int h0   = blockIdx.x * 8;

    if (tid == 0) g_ready[blockIdx.x] = 0;

    // ---- W fill: [k][hi 0..31 | lo 32..63 | pad], stride 72 bf16 ----
    {
        __nv_bfloat16* w = (__nv_bfloat16*)(smc + RW);
        for (int i = tid; i < 32 * 1024; i += 256) {
            int k = i >> 5, n = i & 31;
            int gate = n >> 3;
            const float* W = (gate == 0) ? Wh0 : (gate == 1) ? Wh1
                             : (gate == 2) ? Wh2 : Wh3;
            float v = W[(size_t)k * H_SZ + h0 + (n & 7)];
            __nv_bfloat16 hi = __float2bfloat16(v);
            __nv_bfloat16 lo = __float2bfloat16(v - __bfloat162float(hi));
            w[k * 72 + n]      = hi;
            w[k * 72 + 32 + n] = lo;
        }
    }
    init_barrier();   // flags reset visible; W fill synced chip-wide

    // ---- warp geometry ----
    const int mt    = wid & 3;
    const int npair = wid >> 2;
    const int arow  = ((lane >> 3) & 1) * 8 + (lane & 7);          // 0..15 local
    const uint32_t a_lane = (uint32_t)(arow * 144 + ((lane >> 4) << 4));
    const int brow  = ((lane >> 3) & 1) * 8 + (lane & 7);
    const int bcol  = npair * 16 + ((lane >> 4) << 3);
    const uint32_t bh_lane = (uint32_t)(brow * 144 + bcol * 2);
    const uint32_t bl_lane = bh_lane + 64u;
    const uint32_t Wb = smem_base + RW;
    const uint32_t Ab = smem_base + RA + (uint32_t)mt * 18432u;
    const uint32_t halfoff = npair ? 2304u : 0u;
    const int rbase = blockIdx.x >> 3;
    const int barid = 1 + mt;

    // epilogue mapping: thread -> (batch row b2, h pair hq)
    const int b2 = tid >> 2;
    const int hq = (tid & 3) * 2;
    const size_t hidx = (size_t)b2 * H_SZ + h0 + hq;

    float c0 = 0.f, c1 = 0.f;
    float* sG = (float*)(smc + RG);

    for (int t = 0; t < T_STEPS; ++t) {
        // ---- Xg prefetch into registers ----
        const float* xb = g_xg + ((size_t)t * B_SZ + b2) * G4 + h0 + hq;
        float2 xv0 = __ldcg((const float2*)xb);
        float2 xv1 = __ldcg((const float2*)(xb + 1024));
        float2 xv2 = __ldcg((const float2*)(xb + 2048));
        float2 xv3 = __ldcg((const float2*)(xb + 3072));

        if (t > 0) {
            const int rb   = (t - 1) & 1;
            const int need = t;
            const __nv_bfloat16* src = npair ? g_Hl[rb] : g_Hh[rb];

            float acc0[4] = {0.f, 0.f, 0.f, 0.f};
            float acc1[4] = {0.f, 0.f, 0.f, 0.f};

            // stage chunk at pipeline position p (chunk id rotated)
            auto stage = [&](int p) {
                const int c = (rbase + p) & 15;
                if (lane < 8) {
                    int v = __ldcg(&g_ready[c * 8 + lane]);
                    if (v < need) wait_ready(c * 8 + lane, need);
                }
                __syncwarp();
                const uint32_t dst = Ab + (uint32_t)(p & 3) * 4608u + halfoff;
                const __nv_bfloat16* s0 = src + (size_t)(mt * 16) * H_SZ + c * 64;
                #pragma unroll
                for (int q = 0; q < 4; ++q) {
                    int idx = q * 32 + lane;
                    int row = idx >> 3, k8 = idx & 7;
                    cp16(dst + (uint32_t)(row * 144 + k8 * 16),
                         s0 + (size_t)row * H_SZ + k8 * 8);
                }
                CP_COMMIT();
            };

            stage(0); stage(1); stage(2);

            #pragma unroll 1
            for (int p = 0; p < 16; ++p) {
                CP_WAIT(2);            // own half of position p complete
                bar_named(barid, 64);  // partner's half complete + visible
                const int c = (rbase + p) & 15;
                const uint32_t ah0 = Ab + (uint32_t)(p & 3) * 4608u + a_lane;
                const uint32_t al0 = ah0 + 2304u;
                const uint32_t bo  = Wb + (uint32_t)c * 9216u;
                #pragma unroll
                for (int kt = 0; kt < 4; ++kt) {
                    uint32_t ah[4], al[4], bh[4], bl[4];
                    ldsm_x4 (ah, ah0 + kt * 32);
                    ldsm_x4 (al, al0 + kt * 32);
                    ldsm_x4t(bh, bo + kt * 2304 + bh_lane);
                    ldsm_x4t(bl, bo + kt * 2304 + bl_lane);
                    mma16816(acc0, ah, bh[0], bh[1]);
                    mma16816(acc0, ah, bl[0], bl[1]);
                    mma16816(acc0, al, bh[0], bh[1]);
                    mma16816(acc1, ah, bh[2], bh[3]);
                    mma16816(acc1, ah, bl[2], bl[3]);
                    mma16816(acc1, al, bh[2], bh[3]);
                }
                if (p < 13) stage(p + 3);
                else        CP_COMMIT();   // empty group keeps wait_group math fixed
            }

            // store fragments to sG [64][33]
            {
                int r0  = mt * 16 + (lane >> 2);
                int col = npair * 16 + (lane & 3) * 2;
                sG[r0 * 33 + col]           = acc0[0];
                sG[r0 * 33 + col + 1]       = acc0[1];
                sG[(r0 + 8) * 33 + col]     = acc0[2];
                sG[(r0 + 8) * 33 + col + 1] = acc0[3];
                sG[r0 * 33 + col + 8]           = acc1[0];
                sG[r0 * 33 + col + 9]           = acc1[1];
                sG[(r0 + 8) * 33 + col + 8]     = acc1[2];
                sG[(r0 + 8) * 33 + col + 9]     = acc1[3];
            }
        }
        __syncthreads();   // all warps done; sG visible

        // ---- epilogue: all 256 threads, 2 h-elements each ----
        float gi0, gf0, go0, gc0, gi1, gf1, go1, gc1;
        if (t > 0) {
            const float* gr = sG + b2 * 33;
            gi0 = gr[hq]      + xv0.x;  gi1 = gr[hq + 1]      + xv0.y;
            gf0 = gr[8 + hq]  + xv1.x;  gf1 = gr[8 + hq + 1]  + xv1.y;
            go0 = gr[16 + hq] + xv2.x;  go1 = gr[16 + hq + 1] + xv2.y;
            gc0 = gr[24 + hq] + xv3.x;  gc1 = gr[24 + hq + 1] + xv3.y;
        } else {
            gi0 = xv0.x; gi1 = xv0.y; gf0 = xv1.x; gf1 = xv1.y;
            go0 = xv2.x; go1 = xv2.y; gc0 = xv3.x; gc1 = xv3.y;
        }

        float Iv = __fdividef(1.f, 1.f + __expf(-gi0));
        float Fv = __fdividef(1.f, 1.f + __expf(-gf0));
        float Ov = __fdividef(1.f, 1.f + __expf(-go0));
        float Ct = 1.f - __fdividef(2.f, __expf(2.f * gc0) + 1.f);
        c0 = Fv * c0 + Iv * Ct;
        float Hn0 = Ov * (1.f - __fdividef(2.f, __expf(2.f * c0) + 1.f));

        Iv = __fdividef(1.f, 1.f + __expf(-gi1));
        Fv = __fdividef(1.f, 1.f + __expf(-gf1));
        Ov = __fdividef(1.f, 1.f + __expf(-go1));
        Ct = 1.f - __fdividef(2.f, __expf(2.f * gc1) + 1.f);
        c1 = Fv * c1 + Iv * Ct;
        float Hn1 = Ov * (1.f - __fdividef(2.f, __expf(2.f * c1) + 1.f));

        // publish split-bf16 H first
        {
            const int wb = t & 1;
            __nv_bfloat16 h0b = __float2bfloat16(Hn0);
            __nv_bfloat16 h1b = __float2bfloat16(Hn1);
            __nv_bfloat16 l0b = __float2bfloat16(Hn0 - __bfloat162float(h0b));
            __nv_bfloat16 l1b = __float2bfloat16(Hn1 - __bfloat162float(h1b));
            unsigned hp = (unsigned)*(unsigned short*)&h0b
                        | ((unsigned)*(unsigned short*)&h1b << 16);
            unsigned lp = (unsigned)*(unsigned short*)&l0b
                        | ((unsigned)*(unsigned short*)&l1b << 16);
            *(unsigned*)&g_Hh[wb][hidx] = hp;
            *(unsigned*)&g_Hl[wb][hidx] = lp;
        }
        __threadfence();   // release H writes
        __syncthreads();   // all threads' H published
        if (tid == 0) atomicAdd(&g_ready[blockIdx.x], 1);

        // fp32 outputs after the flag (off the recurrence critical path)
        *(float2*)&out[(size_t)t * BH + hidx] = make_float2(Hn0, Hn1);
        if (t == T_STEPS - 1) {
            size_t base = (size_t)T_STEPS * BH;
            if ((size_t)out_size >= base + (size_t)BH)
                *(float2*)&out[base + hidx] = make_float2(Hn0, Hn1);
            if ((size_t)out_size >= base + 2 * (size_t)BH)
                *(float2*)&out[base + BH + hidx] = make_float2(c0, c1);
        }
    }
}

// ====================================================================
// launch
// ====================================================================
extern "C" void kernel_launch(void* const* d_in, const int* in_sizes, int n_in,
                              void* d_out, int out_size) {
    const float* X   = (const float*)d_in[0];
    const float* Wxi = (const float*)d_in[1];
    const float* Whi = (const float*)d_in[2];
    const float* bi  = (const float*)d_in[3];
    const float* Wxf = (const float*)d_in[4];
    const float* Whf = (const float*)d_in[5];
    const float* bf  = (const float*)d_in[6];
    const float* Wxo = (const float*)d_in[7];
    const float* Who = (const float*)d_in[8];
    const float* bo  = (const float*)d_in[9];
    const float* Wxc = (const float*)d_in[10];
    const float* Whc = (const float*)d_in[11];
    const float* bc  = (const float*)d_in[12];
    float* out = (float*)d_out;

    // Phase 0: split X / Wx into bf16 hi/lo, build bias concat
    int cblocks = (int)((NX4 + NW4) / 256);
    conv_prep<<<cblocks, 256>>>(X, Wxi, Wxf, Wxo, Wxc, bi, bf, bo, bc);

    // Phase 1: Xg = X @ Wxcat + b via tensor cores
    cudaFuncSetAttribute(xg_mma, cudaFuncAttributeMaxDynamicSharedMemorySize,
                         XG_SMEM);
    xg_mma<<<dim3(32, 256), 256, XG_SMEM>>>();

    // Phase 2: persistent recurrence, barrier-free K-loop
    cudaFuncSetAttribute(lstm_rec, cudaFuncAttributeMaxDynamicSharedMemorySize,
                         RT);
    lstm_rec<<<NCTA, 256, RT>>>(Whi, Whf, Who, Whc, out, out_size);
}

// round 10
// speedup vs baseline: 1.1388x; 1.1388x over previous
#include <cuda_runtime.h>
#include <cuda_bf16.h>
#include <cstdint>
#include <math.h>

// ---------------- problem constants ----------------
#define T_STEPS 512
#define B_SZ    64
#define D_SZ    512
#define H_SZ    1024
#define G4      4096          // 4*H
#define BH      (B_SZ*H_SZ)   // 65536
#define NCTA    128

// ---------------- global scratch / sync state ----------------
__device__ float g_xg[(size_t)T_STEPS * B_SZ * G4];   // 512 MB, Xg = X@Wx + b
__device__ __nv_bfloat16 g_Hh[2][BH];                 // H split-bf16 hi, ping-pong
__device__ __nv_bfloat16 g_Hl[2][BH];                 // H split-bf16 lo
__device__ __nv_bfloat16 g_Xh[(size_t)T_STEPS * B_SZ * D_SZ];   // X split hi
__device__ __nv_bfloat16 g_Xl[(size_t)T_STEPS * B_SZ * D_SZ];   // X split lo
__device__ __nv_bfloat16 g_Wxh[(size_t)D_SZ * G4];    // Wx concat split hi
__device__ __nv_bfloat16 g_Wxl[(size_t)D_SZ * G4];    // Wx concat split lo
__device__ float g_bcat[G4];                          // bias concat
__device__ int      g_ready[NCTA];                    // per-CTA step counter
__device__ unsigned g_arrive = 0;
__device__ unsigned g_gen    = 0;

// ---------------- helpers ----------------
__device__ __forceinline__ uint32_t smem_u32(const void* p) {
    uint32_t a;
    asm("{ .reg .u64 t; cvta.to.shared.u64 t, %1; cvt.u32.u64 %0, t; }" : "=r"(a) : "l"(p));
    return a;
}
__device__ __forceinline__ void ldsm_x4(uint32_t* r, uint32_t addr) {
    asm volatile("ldmatrix.sync.aligned.m8n8.x4.shared.b16 {%0,%1,%2,%3}, [%4];"
                 : "=r"(r[0]), "=r"(r[1]), "=r"(r[2]), "=r"(r[3]) : "r"(addr));
}
__device__ __forceinline__ void ldsm_x4t(uint32_t* r, uint32_t addr) {
    asm volatile("ldmatrix.sync.aligned.m8n8.x4.trans.shared.b16 {%0,%1,%2,%3}, [%4];"
                 : "=r"(r[0]), "=r"(r[1]), "=r"(r[2]), "=r"(r[3]) : "r"(addr));
}
__device__ __forceinline__ void mma16816(float* c, const uint32_t* a, uint32_t b0, uint32_t b1) {
    asm volatile(
        "mma.sync.aligned.m16n8k16.row.col.f32.bf16.bf16.f32 "
        "{%0,%1,%2,%3}, {%4,%5,%6,%7}, {%8,%9}, {%0,%1,%2,%3};"
        : "+f"(c[0]), "+f"(c[1]), "+f"(c[2]), "+f"(c[3])
        : "r"(a[0]), "r"(a[1]), "r"(a[2]), "r"(a[3]), "r"(b0), "r"(b1));
}
__device__ __forceinline__ void cp16(uint32_t saddr, const void* g) {
    asm volatile("cp.async.cg.shared.global [%0], [%1], 16;" :: "r"(saddr), "l"(g));
}
#define CP_COMMIT() asm volatile("cp.async.commit_group;" ::: "memory")
#define CP_WAIT(N)  asm volatile("cp.async.wait_group %0;" :: "n"(N) : "memory")

__device__ __forceinline__ void wait_ready(int idx, int target) {
    int v;
    do {
        asm volatile("ld.acquire.gpu.s32 %0, [%1];" : "=r"(v) : "l"(g_ready + idx) : "memory");
        if (v < target) __nanosleep(32);
    } while (v < target);
}

// self-resetting generation barrier (replay-safe)
__device__ __forceinline__ void init_barrier() {
    __syncthreads();
    if (threadIdx.x == 0) {
        __threadfence();
        unsigned gen;
        asm volatile("ld.acquire.gpu.u32 %0, [%1];" : "=r"(gen) : "l"(&g_gen) : "memory");
        unsigned old = atomicAdd(&g_arrive, 1u);
        if (old == NCTA - 1) {
            atomicExch(&g_arrive, 0u);
            __threadfence();
            atomicAdd(&g_gen, 1u);
        } else {
            unsigned cur;
            do {
                __nanosleep(64);
                asm volatile("ld.acquire.gpu.u32 %0, [%1];" : "=r"(cur) : "l"(&g_gen) : "memory");
            } while (cur == gen);
        }
        __threadfence();
    }
    __syncthreads();
}

__device__ __forceinline__ void split2u(float v, unsigned& h, unsigned& l) {
    __nv_bfloat16 hb = __float2bfloat16(v);
    float r = v - __bfloat162float(hb);
    __nv_bfloat16 lb = __float2bfloat16(r);
    h = (unsigned)*reinterpret_cast<unsigned short*>(&hb);
    l = (unsigned)*reinterpret_cast<unsigned short*>(&lb);
}

// ====================================================================
// Kernel 0: split X and Wx (concat) into bf16 hi/lo; build bias concat.
// (unchanged)
// ====================================================================
#define NX4 ((size_t)T_STEPS * B_SZ * D_SZ / 4)      // 4,194,304
#define NW4 ((size_t)D_SZ * G4 / 4)                  // 524,288

__global__ void __launch_bounds__(256) conv_prep(
    const float* __restrict__ X,
    const float* __restrict__ Wx0, const float* __restrict__ Wx1,
    const float* __restrict__ Wx2, const float* __restrict__ Wx3,
    const float* __restrict__ b0p, const float* __restrict__ b1p,
    const float* __restrict__ b2p, const float* __restrict__ b3p)
{
    size_t i = (size_t)blockIdx.x * 256 + threadIdx.x;
    if (i < NX4) {
        float4 v = ((const float4*)X)[i];
        unsigned h0, h1, h2, h3, l0, l1, l2, l3;
        split2u(v.x, h0, l0); split2u(v.y, h1, l1);
        split2u(v.z, h2, l2); split2u(v.w, h3, l3);
        *(uint2*)&g_Xh[i * 4] = make_uint2(h0 | (h1 << 16), h2 | (h3 << 16));
        *(uint2*)&g_Xl[i * 4] = make_uint2(l0 | (l1 << 16), l2 | (l3 << 16));
    } else if (i < NX4 + NW4) {
        size_t d = i - NX4;
        int k  = (int)(d >> 10);
        int c4 = (int)(d & 1023);
        int col  = c4 * 4;
        int gate = col >> 10;
        int n    = col & 1023;
        const float* W = (gate == 0) ? Wx0 : (gate == 1) ? Wx1 : (gate == 2) ? Wx2 : Wx3;
        float4 v = *(const float4*)&W[(size_t)k * 1024 + n];
        unsigned h0, h1, h2, h3, l0, l1, l2, l3;
        split2u(v.x, h0, l0); split2u(v.y, h1, l1);
        split2u(v.z, h2, l2); split2u(v.w, h3, l3);
        *(uint2*)&g_Wxh[d * 4] = make_uint2(h0 | (h1 << 16), h2 | (h3 << 16));
        *(uint2*)&g_Wxl[d * 4] = make_uint2(l0 | (l1 << 16), l2 | (l3 << 16));
    }
    if (i < G4 / 4) {
        int col = (int)i * 4;
        int gate = col >> 10, n = col & 1023;
        const float* bg = (gate == 0) ? b0p : (gate == 1) ? b1p : (gate == 2) ? b2p : b3p;
        ((float4*)g_bcat)[i] = *(const float4*)&bg[n];
    }
}

// ====================================================================
// Kernel 1: Xg = X @ Wxcat + bcat via split-bf16 3-pass mma.sync.
// (unchanged from passing R7 version)
// ====================================================================
#define XA_HI(buf) ((buf)*36864)                   // [128][72] bf16
#define XA_LO(buf) ((buf)*36864 + 18432)
#define XB_HI(buf) (73728 + (buf)*34816)           // [64][136] bf16
#define XB_LO(buf) (73728 + (buf)*34816 + 17408)
#define XG_SMEM    143360

__global__ void __launch_bounds__(256, 1) xg_mma()
{
    extern __shared__ char smc[];
    const uint32_t smem_base = smem_u32(smc);
    const int tid  = threadIdx.x;
    const int wid  = tid >> 5;
    const int lane = tid & 31;
    const int m0   = blockIdx.y * 128;
    const int nb   = blockIdx.x * 128;
    const int mw   = (wid & 3) * 32;
    const int nw   = (wid >> 2) * 64;

    const int arow = ((lane >> 3) & 1) * 8 + (lane & 7);
    const int acol = (lane >> 4) * 8;
    const int brow = ((lane >> 3) & 1) * 8 + (lane & 7);
    const int bcol = (lane >> 4) * 8;

    float acc[2][8][4];
    #pragma unroll
    for (int m = 0; m < 2; ++m)
        #pragma unroll
        for (int n = 0; n < 8; ++n)
            #pragma unroll
            for (int q = 0; q < 4; ++q) acc[m][n][q] = 0.f;

    auto issue_chunk = [&](int s, int buf) {
        #pragma unroll
        for (int i = 0; i < 4; ++i) {
            int idx = tid + i * 256;
            int row = idx >> 3, c8 = (idx & 7) * 8;
            uint32_t sa = smem_base + XA_HI(buf) + (uint32_t)(row * 72 + c8) * 2u;
            size_t go = (size_t)(m0 + row) * D_SZ + s * 64 + c8;
            cp16(sa,          g_Xh + go);
            cp16(sa + 18432u, g_Xl + go);
        }
        #pragma unroll
        for (int i = 0; i < 4; ++i) {
            int idx = tid + i * 256;
            int r = idx >> 4, c8 = (idx & 15) * 8;
            uint32_t sb = smem_base + XB_HI(buf) + (uint32_t)(r * 136 + c8) * 2u;
            size_t go = (size_t)(s * 64 + r) * G4 + nb + c8;
            cp16(sb,          g_Wxh + go);
            cp16(sb + 17408u, g_Wxl + go);
        }
        CP_COMMIT();
    };

    issue_chunk(0, 0);
    #pragma unroll 1
    for (int s = 0; s < 8; ++s) {
        if (s < 7) { issue_chunk(s + 1, (s + 1) & 1); CP_WAIT(1); }
        else       { CP_WAIT(0); }
        __syncthreads();

        const int buf = s & 1;
        const uint32_t Ah = smem_base + XA_HI(buf);
        const uint32_t Bh = smem_base + XB_HI(buf);
        #pragma unroll
        for (int kt = 0; kt < 4; ++kt) {
            uint32_t ah[2][4], al[2][4];
            #pragma unroll
            for (int m = 0; m < 2; ++m) {
                uint32_t ar = Ah + (uint32_t)((mw + m * 16 + arow) * 72 + kt * 16 + acol) * 2u;
                ldsm_x4(ah[m], ar);
                ldsm_x4(al[m], ar + 18432u);
            }
            uint32_t bh[4][4], bl[4][4];
            #pragma unroll
            for (int np = 0; np < 4; ++np) {
                uint32_t br = Bh + (uint32_t)((kt * 16 + brow) * 136 + nw + np * 16 + bcol) * 2u;
                ldsm_x4t(bh[np], br);
                ldsm_x4t(bl[np], br + 17408u);
            }
            #pragma unroll
            for (int m = 0; m < 2; ++m)
                #pragma unroll
                for (int np = 0; np < 4; ++np) {
                    mma16816(acc[m][2*np],   ah[m], bh[np][0], bh[np][1]);
                    mma16816(acc[m][2*np],   ah[m], bl[np][0], bl[np][1]);
                    mma16816(acc[m][2*np],   al[m], bh[np][0], bh[np][1]);
                    mma16816(acc[m][2*np+1], ah[m], bh[np][2], bh[np][3]);
                    mma16816(acc[m][2*np+1], ah[m], bl[np][2], bl[np][3]);
                    mma16816(acc[m][2*np+1], al[m], bh[np][2], bh[np][3]);
                }
        }
        __syncthreads();
    }

    const int r0    = m0 + mw + (lane >> 2);
    const int cbase = nb + nw + (lane & 3) * 2;
    #pragma unroll
    for (int m = 0; m < 2; ++m) {
        #pragma unroll
        for (int nt = 0; nt < 8; ++nt) {
            int col = cbase + nt * 8;
            float b0 = g_bcat[col], b1 = g_bcat[col + 1];
            int rr = r0 + m * 16;
            float* p0 = g_xg + (size_t)rr * G4 + col;
            float* p1 = g_xg + (size_t)(rr + 8) * G4 + col;
            *(float2*)p0 = make_float2(acc[m][nt][0] + b0, acc[m][nt][1] + b1);
            *(float2*)p1 = make_float2(acc[m][nt][2] + b0, acc[m][nt][3] + b1);
        }
    }
}

// ====================================================================
// Kernel 2: persistent recurrence v5 — K-split warps, register-resident B.
// Warp w owns K-slice [w*128,+128), computes partial G[64,32] over it.
// B (Wh slice hi+lo) fragments extracted ONCE into 128 registers at init.
// Per step: warp-private stream of its H slice (4 sub-chunks of K=32,
// 2-deep cp.async ring, stride-40 layout), lane-parallel flag waits,
// ZERO CTA barriers in the K-loop. Then one sync + 8-way partial
// reduction in SMEM feeds the wide epilogue.
// ====================================================================

#define RA    0                       // rings: 8 warps x 20480 = 163840
                                      // (init: W hi at 0, W lo at 81920)
#define RG    163840                  // partials: 8 x 64 x 33 f32 = 67584
#define RT    231424                  // total dynamic smem

__global__ void __launch_bounds__(256, 1) lstm_rec(
    const float* __restrict__ Wh0, const float* __restrict__ Wh1,
    const float* __restrict__ Wh2, const float* __restrict__ Wh3,
    float* __restrict__ out, int out_size)
{
    extern __shared__ char smc[];
    const uint32_t smem_base = smem_u32(smc);
    const int tid  = threadIdx.x;
    const int wid  = tid >> 5;
    const int lane = tid & 31;
    const int h0   = blockIdx.x * 8;

    if (tid == 0) g_ready[blockIdx.x] = 0;

    // ---- stage W slice (stride 40, hi at 0 / lo at 81920) ----
    {
        __nv_bfloat16* wh = (__nv_bfloat16*)(smc);
        __nv_bfloat16* wl = (__nv_bfloat16*)(smc + 81920);
        for (int i = tid; i < 32 * 1024; i += 256) {
            int k = i >> 5, n = i & 31;
            int gate = n >> 3;
            const float* W = (gate == 0) ? Wh0 : (gate == 1) ? Wh1
                             : (gate == 2) ? Wh2 : Wh3;
            float v = W[(size_t)k * H_SZ + h0 + (n & 7)];
            __nv_bfloat16 hi = __float2bfloat16(v);
            __nv_bfloat16 lo = __float2bfloat16(v - __bfloat162float(hi));
            wh[k * 40 + n] = hi;
            wl[k * 40 + n] = lo;
        }
    }
    __syncthreads();

    // ---- extract register-resident B fragments (once) ----
    const int brow  = ((lane >> 3) & 1) * 8 + (lane & 7);
    const int bcol0 = (lane >> 4) * 8;
    uint32_t bhi[8][8], blo[8][8];     // [k-tile][n-tile*2 + j]
    #pragma unroll
    for (int kt = 0; kt < 8; ++kt) {
        #pragma unroll
        for (int half = 0; half < 2; ++half) {
            uint32_t off = (uint32_t)((wid * 128 + kt * 16 + brow) * 40
                                      + half * 16 + bcol0) * 2u;
            ldsm_x4t(&bhi[kt][half * 4], smem_base + off);
            ldsm_x4t(&blo[kt][half * 4], smem_base + 81920u + off);
        }
    }
    init_barrier();   // flags reset visible; W area free for rings after this

    // ---- per-warp ring / ldsm geometry ----
    const uint32_t ring = smem_base + RA + (uint32_t)wid * 20480u;
    const int arow  = ((lane >> 3) & 1) * 8 + (lane & 7);
    const uint32_t a_lane = (uint32_t)(arow * 80 + ((lane >> 4) << 4));
    // staging lane mapping: 8 x 16B per half
    const int srow  = lane >> 2;                 // rows lane>>2 + q*8
    const int scoff = (lane & 3) * 8;
    // epilogue mapping
    const int b2 = tid >> 2;
    const int hq = (tid & 3) * 2;
    const size_t hidx = (size_t)b2 * H_SZ + h0 + hq;

    float* P  = (float*)(smc + RG);
    float* Pw = P + wid * 2112;       // this warp's partial [64][33]

    float c0 = 0.f, c1 = 0.f;

    for (int t = 0; t < T_STEPS; ++t) {
        float acc[4][4][4];
        #pragma unroll
        for (int m = 0; m < 4; ++m)
            #pragma unroll
            for (int n = 0; n < 4; ++n)
                #pragma unroll
                for (int q = 0; q < 4; ++q) acc[m][n][q] = 0.f;

        if (t > 0) {
            const int rb = (t - 1) & 1;
            const __nv_bfloat16* Hh = g_Hh[rb];
            const __nv_bfloat16* Hl = g_Hl[rb];

            auto stage = [&](int sc) {
                if (lane < 4) {
                    int idx = wid * 16 + sc * 4 + lane;
                    int v = __ldcg(&g_ready[idx]);
                    if (v < t) wait_ready(idx, t);
                }
                __syncwarp();
                const uint32_t dh = ring + (uint32_t)(sc & 1) * 10240u;
                const int k0 = wid * 128 + sc * 32;
                #pragma unroll
                for (int q = 0; q < 8; ++q) {
                    int row = srow + q * 8;
                    uint32_t doff = (uint32_t)(row * 80 + scoff * 2);
                    size_t  soff = (size_t)row * H_SZ + k0 + scoff;
                    cp16(dh + doff,          Hh + soff);
                    cp16(dh + 5120u + doff,  Hl + soff);
                }
                CP_COMMIT();
            };

            stage(0); stage(1);

            #pragma unroll
            for (int sc = 0; sc < 4; ++sc) {
                if (sc < 3) CP_WAIT(1); else CP_WAIT(0);
                const uint32_t base = ring + (uint32_t)(sc & 1) * 10240u;
                #pragma unroll
                for (int ktl = 0; ktl < 2; ++ktl) {
                    const int kt = sc * 2 + ktl;
                    #pragma unroll
                    for (int mt = 0; mt < 4; ++mt) {
                        uint32_t ah[4], al[4];
                        uint32_t aa = base + (uint32_t)(mt * 16 * 80)
                                    + (uint32_t)(ktl * 32) + a_lane;
                        ldsm_x4(ah, aa);
                        ldsm_x4(al, aa + 5120u);
                        #pragma unroll
                        for (int nt = 0; nt < 4; ++nt) {
                            mma16816(acc[mt][nt], ah, bhi[kt][nt*2], bhi[kt][nt*2+1]);
                            mma16816(acc[mt][nt], ah, blo[kt][nt*2], blo[kt][nt*2+1]);
                            mma16816(acc[mt][nt], al, bhi[kt][nt*2], bhi[kt][nt*2+1]);
                        }
                    }
                }
                if (sc < 2) stage(sc + 2);
            }

            // store this warp's partial [64][33]
            #pragma unroll
            for (int mt = 0; mt < 4; ++mt) {
                int r0 = mt * 16 + (lane >> 2);
                #pragma unroll
                for (int nt = 0; nt < 4; ++nt) {
                    int col = nt * 8 + (lane & 3) * 2;
                    Pw[r0 * 33 + col]           = acc[mt][nt][0];
                    Pw[r0 * 33 + col + 1]       = acc[mt][nt][1];
                    Pw[(r0 + 8) * 33 + col]     = acc[mt][nt][2];
                    Pw[(r0 + 8) * 33 + col + 1] = acc[mt][nt][3];
                }
            }
        }

        // Xg loads (latency covered by the sync below)
        const float* xb = g_xg + ((size_t)t * B_SZ + b2) * G4 + h0 + hq;
        float2 xv0 = __ldcg((const float2*)xb);
        float2 xv1 = __ldcg((const float2*)(xb + 1024));
        float2 xv2 = __ldcg((const float2*)(xb + 2048));
        float2 xv3 = __ldcg((const float2*)(xb + 3072));

        __syncthreads();   // partials visible

        // ---- reduce 8 partials + gate math (all 256 threads) ----
        float gi0 = xv0.x, gi1 = xv0.y, gf0 = xv1.x, gf1 = xv1.y;
        float go0 = xv2.x, go1 = xv2.y, gc0 = xv3.x, gc1 = xv3.y;
        if (t > 0) {
            #pragma unroll
            for (int w = 0; w < 8; ++w) {
                const float* pr = P + w * 2112 + b2 * 33;
                gi0 += pr[hq];      gi1 += pr[hq + 1];
                gf0 += pr[8 + hq];  gf1 += pr[8 + hq + 1];
                go0 += pr[16 + hq]; go1 += pr[16 + hq + 1];
                gc0 += pr[24 + hq]; gc1 += pr[24 + hq + 1];
            }
        }

        float Iv = __fdividef(1.f, 1.f + __expf(-gi0));
        float Fv = __fdividef(1.f, 1.f + __expf(-gf0));
        float Ov = __fdividef(1.f, 1.f + __expf(-go0));
        float Ct = 1.f - __fdividef(2.f, __expf(2.f * gc0) + 1.f);
        c0 = Fv * c0 + Iv * Ct;
        float Hn0 = Ov * (1.f - __fdividef(2.f, __expf(2.f * c0) + 1.f));

        Iv = __fdividef(1.f, 1.f + __expf(-gi1));
        Fv = __fdividef(1.f, 1.f + __expf(-gf1));
        Ov = __fdividef(1.f, 1.f + __expf(-go1));
        Ct = 1.f - __fdividef(2.f, __expf(2.f * gc1) + 1.f);
        c1 = Fv * c1 + Iv * Ct;
        float Hn1 = Ov * (1.f - __fdividef(2.f, __expf(2.f * c1) + 1.f));

        // publish split-bf16 H
        {
            const int wb = t & 1;
            __nv_bfloat16 h0b = __float2bfloat16(Hn0);
            __nv_bfloat16 h1b = __float2bfloat16(Hn1);
            __nv_bfloat16 l0b = __float2bfloat16(Hn0 - __bfloat162float(h0b));
            __nv_bfloat16 l1b = __float2bfloat16(Hn1 - __bfloat162float(h1b));
            unsigned hp = (unsigned)*(unsigned short*)&h0b
                        | ((unsigned)*(unsigned short*)&h1b << 16);
            unsigned lp = (unsigned)*(unsigned short*)&l0b
                        | ((unsigned)*(unsigned short*)&l1b << 16);
            *(unsigned*)&g_Hh[wb][hidx] = hp;
            *(unsigned*)&g_Hl[wb][hidx] = lp;
        }
        __threadfence();   // release H writes
        __syncthreads();   // all H published; partial buffers reusable
        if (tid == 0) atomicAdd(&g_ready[blockIdx.x], 1);

        // fp32 outputs after the flag
        *(float2*)&out[(size_t)t * BH + hidx] = make_float2(Hn0, Hn1);
        if (t == T_STEPS - 1) {
            size_t base = (size_t)T_STEPS * BH;
            if ((size_t)out_size >= base + (size_t)BH)
                *(float2*)&out[base + hidx] = make_float2(Hn0, Hn1);
            if ((size_t)out_size >= base + 2 * (size_t)BH)
                *(float2*)&out[base + BH + hidx] = make_float2(c0, c1);
        }
    }
}

// ====================================================================
// launch
// ====================================================================
extern "C" void kernel_launch(void* const* d_in, const int* in_sizes, int n_in,
                              void* d_out, int out_size) {
    const float* X   = (const float*)d_in[0];
    const float* Wxi = (const float*)d_in[1];
    const float* Whi = (const float*)d_in[2];
    const float* bi  = (const float*)d_in[3];
    const float* Wxf = (const float*)d_in[4];
    const float* Whf = (const float*)d_in[5];
    const float* bf  = (const float*)d_in[6];
    const float* Wxo = (const float*)d_in[7];
    const float* Who = (const float*)d_in[8];
    const float* bo  = (const float*)d_in[9];
    const float* Wxc = (const float*)d_in[10];
    const float* Whc = (const float*)d_in[11];
    const float* bc  = (const float*)d_in[12];
    float* out = (float*)d_out;

    // Phase 0: split X / Wx into bf16 hi/lo, build bias concat
    int cblocks = (int)((NX4 + NW4) / 256);
    conv_prep<<<cblocks, 256>>>(X, Wxi, Wxf, Wxo, Wxc, bi, bf, bo, bc);

    // Phase 1: Xg = X @ Wxcat + b via tensor cores
    cudaFuncSetAttribute(xg_mma, cudaFuncAttributeMaxDynamicSharedMemorySize,
                         XG_SMEM);
    xg_mma<<<dim3(32, 256), 256, XG_SMEM>>>();

    // Phase 2: persistent recurrence, K-split warps + resident B
    cudaFuncSetAttribute(lstm_rec, cudaFuncAttributeMaxDynamicSharedMemorySize,
                         RT);
    lstm_rec<<<NCTA, 256, RT>>>(Whi, Whf, Who, Whc, out, out_size);
}

// round 12
// speedup vs baseline: 1.4875x; 1.3063x over previous
#include <cuda_runtime.h>
#include <cuda_bf16.h>
#include <cuda_fp16.h>
#include <cstdint>
#include <math.h>

// ---------------- problem constants ----------------
#define T_STEPS 512
#define B_SZ    64
#define D_SZ    512
#define H_SZ    1024
#define G4      4096          // 4*H
#define BH      (B_SZ*H_SZ)   // 65536
#define NCTA    128

// ---------------- global scratch / sync state ----------------
__device__ float g_xg[(size_t)T_STEPS * B_SZ * G4];   // 512 MB, Xg = X@Wx + b
__device__ __half g_Hf[2][BH];                        // H fp16, ping-pong
__device__ __nv_bfloat16 g_Xh[(size_t)T_STEPS * B_SZ * D_SZ];   // X split hi
__device__ __nv_bfloat16 g_Xl[(size_t)T_STEPS * B_SZ * D_SZ];   // X split lo
__device__ __nv_bfloat16 g_Wxh[(size_t)D_SZ * G4];    // Wx concat split hi
__device__ __nv_bfloat16 g_Wxl[(size_t)D_SZ * G4];    // Wx concat split lo
__device__ float g_bcat[G4];                          // bias concat
__device__ int      g_ready[NCTA];                    // per-CTA step counter
__device__ unsigned g_arrive = 0;
__device__ unsigned g_gen    = 0;

// ---------------- helpers ----------------
__device__ __forceinline__ uint32_t smem_u32(const void* p) {
    uint32_t a;
    asm("{ .reg .u64 t; cvta.to.shared.u64 t, %1; cvt.u32.u64 %0, t; }" : "=r"(a) : "l"(p));
    return a;
}
__device__ __forceinline__ void ldsm_x4(uint32_t* r, uint32_t addr) {
    asm volatile("ldmatrix.sync.aligned.m8n8.x4.shared.b16 {%0,%1,%2,%3}, [%4];"
                 : "=r"(r[0]), "=r"(r[1]), "=r"(r[2]), "=r"(r[3]) : "r"(addr));
}
__device__ __forceinline__ void ldsm_x4t(uint32_t* r, uint32_t addr) {
    asm volatile("ldmatrix.sync.aligned.m8n8.x4.trans.shared.b16 {%0,%1,%2,%3}, [%4];"
                 : "=r"(r[0]), "=r"(r[1]), "=r"(r[2]), "=r"(r[3]) : "r"(addr));
}
// bf16 mma (xg path)
__device__ __forceinline__ void mma16816(float* c, const uint32_t* a, uint32_t b0, uint32_t b1) {
    asm volatile(
        "mma.sync.aligned.m16n8k16.row.col.f32.bf16.bf16.f32 "
        "{%0,%1,%2,%3}, {%4,%5,%6,%7}, {%8,%9}, {%0,%1,%2,%3};"
        : "+f"(c[0]), "+f"(c[1]), "+f"(c[2]), "+f"(c[3])
        : "r"(a[0]), "r"(a[1]), "r"(a[2]), "r"(a[3]), "r"(b0), "r"(b1));
}
// fp16 mma (recurrence path)
__device__ __forceinline__ void mma16816h(float* c, const uint32_t* a, uint32_t b0, uint32_t b1) {
    asm volatile(
        "mma.sync.aligned.m16n8k16.row.col.f32.f16.f16.f32 "
        "{%0,%1,%2,%3}, {%4,%5,%6,%7}, {%8,%9}, {%0,%1,%2,%3};"
        : "+f"(c[0]), "+f"(c[1]), "+f"(c[2]), "+f"(c[3])
        : "r"(a[0]), "r"(a[1]), "r"(a[2]), "r"(a[3]), "r"(b0), "r"(b1));
}
__device__ __forceinline__ void cp16(uint32_t saddr, const void* g) {
    asm volatile("cp.async.cg.shared.global [%0], [%1], 16;" :: "r"(saddr), "l"(g));
}
#define CP_COMMIT() asm volatile("cp.async.commit_group;" ::: "memory")
#define CP_WAIT(N)  asm volatile("cp.async.wait_group %0;" :: "n"(N) : "memory")

__device__ __forceinline__ void wait_ready(int idx, int target) {
    int v;
    do {
        asm volatile("ld.acquire.gpu.s32 %0, [%1];" : "=r"(v) : "l"(g_ready + idx) : "memory");
        if (v < target) __nanosleep(32);
    } while (v < target);
}

// self-resetting generation barrier (replay-safe)
__device__ __forceinline__ void init_barrier() {
    __syncthreads();
    if (threadIdx.x == 0) {
        __threadfence();
        unsigned gen;
        asm volatile("ld.acquire.gpu.u32 %0, [%1];" : "=r"(gen) : "l"(&g_gen) : "memory");
        unsigned old = atomicAdd(&g_arrive, 1u);
        if (old == NCTA - 1) {
            atomicExch(&g_arrive, 0u);
            __threadfence();
            atomicAdd(&g_gen, 1u);
        } else {
            unsigned cur;
            do {
                __nanosleep(64);
                asm volatile("ld.acquire.gpu.u32 %0, [%1];" : "=r"(cur) : "l"(&g_gen) : "memory");
            } while (cur == gen);
        }
        __threadfence();
    }
    __syncthreads();
}

__device__ __forceinline__ void split2u(float v, unsigned& h, unsigned& l) {
    __nv_bfloat16 hb = __float2bfloat16(v);
    float r = v - __bfloat162float(hb);
    __nv_bfloat16 lb = __float2bfloat16(r);
    h = (unsigned)*reinterpret_cast<unsigned short*>(&hb);
    l = (unsigned)*reinterpret_cast<unsigned short*>(&lb);
}

// ====================================================================
// Kernel 0: split X and Wx (concat) into bf16 hi/lo; build bias concat.
// (unchanged)
// ====================================================================
#define NX4 ((size_t)T_STEPS * B_SZ * D_SZ / 4)      // 4,194,304
#define NW4 ((size_t)D_SZ * G4 / 4)                  // 524,288

__global__ void __launch_bounds__(256) conv_prep(
    const float* __restrict__ X,
    const float* __restrict__ Wx0, const float* __restrict__ Wx1,
    const float* __restrict__ Wx2, const float* __restrict__ Wx3,
    const float* __restrict__ b0p, const float* __restrict__ b1p,
    const float* __restrict__ b2p, const float* __restrict__ b3p)
{
    size_t i = (size_t)blockIdx.x * 256 + threadIdx.x;
    if (i < NX4) {
        float4 v = ((const float4*)X)[i];
        unsigned h0, h1, h2, h3, l0, l1, l2, l3;
        split2u(v.x, h0, l0); split2u(v.y, h1, l1);
        split2u(v.z, h2, l2); split2u(v.w, h3, l3);
        *(uint2*)&g_Xh[i * 4] = make_uint2(h0 | (h1 << 16), h2 | (h3 << 16));
        *(uint2*)&g_Xl[i * 4] = make_uint2(l0 | (l1 << 16), l2 | (l3 << 16));
    } else if (i < NX4 + NW4) {
        size_t d = i - NX4;
        int k  = (int)(d >> 10);
        int c4 = (int)(d & 1023);
        int col  = c4 * 4;
        int gate = col >> 10;
        int n    = col & 1023;
        const float* W = (gate == 0) ? Wx0 : (gate == 1) ? Wx1 : (gate == 2) ? Wx2 : Wx3;
        float4 v = *(const float4*)&W[(size_t)k * 1024 + n];
        unsigned h0, h1, h2, h3, l0, l1, l2, l3;
        split2u(v.x, h0, l0); split2u(v.y, h1, l1);
        split2u(v.z, h2, l2); split2u(v.w, h3, l3);
        *(uint2*)&g_Wxh[d * 4] = make_uint2(h0 | (h1 << 16), h2 | (h3 << 16));
        *(uint2*)&g_Wxl[d * 4] = make_uint2(l0 | (l1 << 16), l2 | (l3 << 16));
    }
    if (i < G4 / 4) {
        int col = (int)i * 4;
        int gate = col >> 10, n = col & 1023;
        const float* bg = (gate == 0) ? b0p : (gate == 1) ? b1p : (gate == 2) ? b2p : b3p;
        ((float4*)g_bcat)[i] = *(const float4*)&bg[n];
    }
}

// ====================================================================
// Kernel 1: Xg = X @ Wxcat + bcat via split-bf16 3-pass mma.sync.
// (unchanged from passing R7 version — keeps Xg accurate, it dominates)
// ====================================================================
#define XA_HI(buf) ((buf)*36864)                   // [128][72] bf16
#define XA_LO(buf) ((buf)*36864 + 18432)
#define XB_HI(buf) (73728 + (buf)*34816)           // [64][136] bf16
#define XB_LO(buf) (73728 + (buf)*34816 + 17408)
#define XG_SMEM    143360

__global__ void __launch_bounds__(256, 1) xg_mma()
{
    extern __shared__ char smc[];
    const uint32_t smem_base = smem_u32(smc);
    const int tid  = threadIdx.x;
    const int wid  = tid >> 5;
    const int lane = tid & 31;
    const int m0   = blockIdx.y * 128;
    const int nb   = blockIdx.x * 128;
    const int mw   = (wid & 3) * 32;
    const int nw   = (wid >> 2) * 64;

    const int arow = ((lane >> 3) & 1) * 8 + (lane & 7);
    const int acol = (lane >> 4) * 8;
    const int brow = ((lane >> 3) & 1) * 8 + (lane & 7);
    const int bcol = (lane >> 4) * 8;

    float acc[2][8][4];
    #pragma unroll
    for (int m = 0; m < 2; ++m)
        #pragma unroll
        for (int n = 0; n < 8; ++n)
            #pragma unroll
            for (int q = 0; q < 4; ++q) acc[m][n][q] = 0.f;

    auto issue_chunk = [&](int s, int buf) {
        #pragma unroll
        for (int i = 0; i < 4; ++i) {
            int idx = tid + i * 256;
            int row = idx >> 3, c8 = (idx & 7) * 8;
            uint32_t sa = smem_base + XA_HI(buf) + (uint32_t)(row * 72 + c8) * 2u;
            size_t go = (size_t)(m0 + row) * D_SZ + s * 64 + c8;
            cp16(sa,          g_Xh + go);
            cp16(sa + 18432u, g_Xl + go);
        }
        #pragma unroll
        for (int i = 0; i < 4; ++i) {
            int idx = tid + i * 256;
            int r = idx >> 4, c8 = (idx & 15) * 8;
            uint32_t sb = smem_base + XB_HI(buf) + (uint32_t)(r * 136 + c8) * 2u;
            size_t go = (size_t)(s * 64 + r) * G4 + nb + c8;
            cp16(sb,          g_Wxh + go);
            cp16(sb + 17408u, g_Wxl + go);
        }
        CP_COMMIT();
    };

    issue_chunk(0, 0);
    #pragma unroll 1
    for (int s = 0; s < 8; ++s) {
        if (s < 7) { issue_chunk(s + 1, (s + 1) & 1); CP_WAIT(1); }
        else       { CP_WAIT(0); }
        __syncthreads();

        const int buf = s & 1;
        const uint32_t Ah = smem_base + XA_HI(buf);
        const uint32_t Bh = smem_base + XB_HI(buf);
        #pragma unroll
        for (int kt = 0; kt < 4; ++kt) {
            uint32_t ah[2][4], al[2][4];
            #pragma unroll
            for (int m = 0; m < 2; ++m) {
                uint32_t ar = Ah + (uint32_t)((mw + m * 16 + arow) * 72 + kt * 16 + acol) * 2u;
                ldsm_x4(ah[m], ar);
                ldsm_x4(al[m], ar + 18432u);
            }
            uint32_t bh[4][4], bl[4][4];
            #pragma unroll
            for (int np = 0; np < 4; ++np) {
                uint32_t br = Bh + (uint32_t)((kt * 16 + brow) * 136 + nw + np * 16 + bcol) * 2u;
                ldsm_x4t(bh[np], br);
                ldsm_x4t(bl[np], br + 17408u);
            }
            #pragma unroll
            for (int m = 0; m < 2; ++m)
                #pragma unroll
                for (int np = 0; np < 4; ++np) {
                    mma16816(acc[m][2*np],   ah[m], bh[np][0], bh[np][1]);
                    mma16816(acc[m][2*np],   ah[m], bl[np][0], bl[np][1]);
                    mma16816(acc[m][2*np],   al[m], bh[np][0], bh[np][1]);
                    mma16816(acc[m][2*np+1], ah[m], bh[np][2], bh[np][3]);
                    mma16816(acc[m][2*np+1], ah[m], bl[np][2], bl[np][3]);
                    mma16816(acc[m][2*np+1], al[m], bh[np][2], bh[np][3]);
                }
        }
        __syncthreads();
    }

    const int r0    = m0 + mw + (lane >> 2);
    const int cbase = nb + nw + (lane & 3) * 2;
    #pragma unroll
    for (int m = 0; m < 2; ++m) {
        #pragma unroll
        for (int nt = 0; nt < 8; ++nt) {
            int col = cbase + nt * 8;
            float b0 = g_bcat[col], b1 = g_bcat[col + 1];
            int rr = r0 + m * 16;
            float* p0 = g_xg + (size_t)rr * G4 + col;
            float* p1 = g_xg + (size_t)(rr + 8) * G4 + col;
            *(float2*)p0 = make_float2(acc[m][nt][0] + b0, acc[m][nt][1] + b1);
            *(float2*)p1 = make_float2(acc[m][nt][2] + b0, acc[m][nt][3] + b1);
        }
    }
}

// ====================================================================
// Kernel 2: persistent recurrence v6b — single-pass fp16, K-split warps,
// register-resident B. A-ring row stride 80 BYTES (40 halves) so every
// 16B cp.async target stays 16B-aligned (the R11 stride-72 layout
// faulted on odd rows: 72 mod 16 = 8). ldsm row offsets mod 128 are
// {0,80,32,112,64,16,96,48} — conflict-free.
// H stored as ONE fp16 array (ping-pong): 16MB/step L2 traffic.
// W staged fp16 in the ring area during init (81920 B, exact fit).
// ====================================================================

#define RG6   81920                   // partials: 8 x 64 x 33 f32 = 67584
#define RT6   149504                  // total dynamic smem

__global__ void __launch_bounds__(256, 1) lstm_rec(
    const float* __restrict__ Wh0, const float* __restrict__ Wh1,
    const float* __restrict__ Wh2, const float* __restrict__ Wh3,
    float* __restrict__ out, int out_size)
{
    extern __shared__ char smc[];
    const uint32_t smem_base = smem_u32(smc);
    const int tid  = threadIdx.x;
    const int wid  = tid >> 5;
    const int lane = tid & 31;
    const int h0   = blockIdx.x * 8;

    if (tid == 0) g_ready[blockIdx.x] = 0;

    // ---- stage W slice fp16 (stride 40 halves, temp at offset 0) ----
    {
        __half* w = (__half*)smc;
        for (int i = tid; i < 32 * 1024; i += 256) {
            int k = i >> 5, n = i & 31;
            int gate = n >> 3;
            const float* W = (gate == 0) ? Wh0 : (gate == 1) ? Wh1
                             : (gate == 2) ? Wh2 : Wh3;
            w[k * 40 + n] = __float2half_rn(W[(size_t)k * H_SZ + h0 + (n & 7)]);
        }
    }
    __syncthreads();

    // ---- extract register-resident B fragments (once) ----
    const int brow  = ((lane >> 3) & 1) * 8 + (lane & 7);
    const int bcol0 = (lane >> 4) * 8;
    uint32_t bf[8][8];                 // [k-tile][half*4 + j]
    #pragma unroll
    for (int kt = 0; kt < 8; ++kt) {
        #pragma unroll
        for (int half = 0; half < 2; ++half) {
            uint32_t off = (uint32_t)((wid * 128 + kt * 16 + brow) * 40
                                      + half * 16 + bcol0) * 2u;
            ldsm_x4t(&bf[kt][half * 4], smem_base + off);
        }
    }
    init_barrier();   // flags reset visible; W area now reusable as rings

    // ---- per-warp ring / ldsm geometry (stride 80 bytes) ----
    const uint32_t ring = smem_base + (uint32_t)wid * 10240u;   // 2 x 5120B
    const int arow  = ((lane >> 3) & 1) * 8 + (lane & 7);
    const uint32_t a_lane = (uint32_t)(arow * 80 + ((lane >> 4) << 4));
    // epilogue mapping
    const int b2 = tid >> 2;
    const int hq = (tid & 3) * 2;
    const size_t hidx = (size_t)b2 * H_SZ + h0 + hq;

    float* P  = (float*)(smc + RG6);
    float* Pw = P + wid * 2112;       // this warp's partial [64][33]

    float c0 = 0.f, c1 = 0.f;

    for (int t = 0; t < T_STEPS; ++t) {
        float acc[4][4][4];
        #pragma unroll
        for (int m = 0; m < 4; ++m)
            #pragma unroll
            for (int n = 0; n < 4; ++n)
                #pragma unroll
                for (int q = 0; q < 4; ++q) acc[m][n][q] = 0.f;

        if (t > 0) {
            const __half* Hf = g_Hf[(t - 1) & 1];

            auto stage = [&](int sc) {
                if (lane < 4) {
                    int idx = wid * 16 + sc * 4 + lane;
                    int v = __ldcg(&g_ready[idx]);
                    if (v < t) wait_ready(idx, t);
                }
                __syncwarp();
                const uint32_t dst = ring + (uint32_t)(sc & 1) * 5120u;
                const int k0 = wid * 128 + sc * 32;
                #pragma unroll
                for (int q = 0; q < 8; ++q) {
                    int idx = q * 32 + lane;
                    int row = idx >> 2, c4 = idx & 3;
                    cp16(dst + (uint32_t)(row * 80 + c4 * 16),
                         Hf + (size_t)row * H_SZ + k0 + c4 * 8);
                }
                CP_COMMIT();
            };

            stage(0); stage(1);

            #pragma unroll
            for (int sc = 0; sc < 4; ++sc) {
                if (sc < 3) CP_WAIT(1); else CP_WAIT(0);
                const uint32_t base = ring + (uint32_t)(sc & 1) * 5120u;
                #pragma unroll
                for (int ktl = 0; ktl < 2; ++ktl) {
                    const int kt = sc * 2 + ktl;
                    #pragma unroll
                    for (int mt = 0; mt < 4; ++mt) {
                        uint32_t av[4];
                        ldsm_x4(av, base + (uint32_t)(mt * 1280)
                                     + (uint32_t)(ktl * 32) + a_lane);
                        #pragma unroll
                        for (int nt = 0; nt < 4; ++nt)
                            mma16816h(acc[mt][nt], av, bf[kt][nt*2], bf[kt][nt*2+1]);
                    }
                }
                if (sc < 2) stage(sc + 2);
            }

            // store this warp's partial [64][33]
            #pragma unroll
            for (int mt = 0; mt < 4; ++mt) {
                int r0 = mt * 16 + (lane >> 2);
                #pragma unroll
                for (int nt = 0; nt < 4; ++nt) {
                    int col = nt * 8 + (lane & 3) * 2;
                    Pw[r0 * 33 + col]           = acc[mt][nt][0];
                    Pw[r0 * 33 + col + 1]       = acc[mt][nt][1];
                    Pw[(r0 + 8) * 33 + col]     = acc[mt][nt][2];
                    Pw[(r0 + 8) * 33 + col + 1] = acc[mt][nt][3];
                }
            }
        }

        // Xg loads (latency covered by the sync below)
        const float* xb = g_xg + ((size_t)t * B_SZ + b2) * G4 + h0 + hq;
        float2 xv0 = __ldcg((const float2*)xb);
        float2 xv1 = __ldcg((const float2*)(xb + 1024));
        float2 xv2 = __ldcg((const float2*)(xb + 2048));
        float2 xv3 = __ldcg((const float2*)(xb + 3072));

        __syncthreads();   // partials visible

        // ---- reduce 8 partials + gate math (all 256 threads) ----
        float gi0 = xv0.x, gi1 = xv0.y, gf0 = xv1.x, gf1 = xv1.y;
        float go0 = xv2.x, go1 = xv2.y, gc0 = xv3.x, gc1 = xv3.y;
        if (t > 0) {
            #pragma unroll
            for (int w = 0; w < 8; ++w) {
                const float* pr = P + w * 2112 + b2 * 33;
                gi0 += pr[hq];      gi1 += pr[hq + 1];
                gf0 += pr[8 + hq];  gf1 += pr[8 + hq + 1];
                go0 += pr[16 + hq]; go1 += pr[16 + hq + 1];
                gc0 += pr[24 + hq]; gc1 += pr[24 + hq + 1];
            }
        }

        float Iv = __fdividef(1.f, 1.f + __expf(-gi0));
        float Fv = __fdividef(1.f, 1.f + __expf(-gf0));
        float Ov = __fdividef(1.f, 1.f + __expf(-go0));
        float Ct = 1.f - __fdividef(2.f, __expf(2.f * gc0) + 1.f);
        c0 = Fv * c0 + Iv * Ct;
        float Hn0 = Ov * (1.f - __fdividef(2.f, __expf(2.f * c0) + 1.f));

        Iv = __fdividef(1.f, 1.f + __expf(-gi1));
        Fv = __fdividef(1.f, 1.f + __expf(-gf1));
        Ov = __fdividef(1.f, 1.f + __expf(-go1));
        Ct = 1.f - __fdividef(2.f, __expf(2.f * gc1) + 1.f);
        c1 = Fv * c1 + Iv * Ct;
        float Hn1 = Ov * (1.f - __fdividef(2.f, __expf(2.f * c1) + 1.f));

        // publish fp16 H
        {
            const int wb = t & 1;
            __half h0h = __float2half_rn(Hn0);
            __half h1h = __float2half_rn(Hn1);
            unsigned hp = (unsigned)*(unsigned short*)&h0h
                        | ((unsigned)*(unsigned short*)&h1h << 16);
            *(unsigned*)&g_Hf[wb][hidx] = hp;
        }
        __threadfence();   // release H writes
        __syncthreads();   // all threads' H published
        if (tid == 0) atomicAdd(&g_ready[blockIdx.x], 1);

        // fp32 outputs after the flag (off the recurrence critical path)
        *(float2*)&out[(size_t)t * BH + hidx] = make_float2(Hn0, Hn1);
        if (t == T_STEPS - 1) {
            size_t base = (size_t)T_STEPS * BH;
            if ((size_t)out_size >= base + (size_t)BH)
                *(float2*)&out[base + hidx] = make_float2(Hn0, Hn1);
            if ((size_t)out_size >= base + 2 * (size_t)BH)
                *(float2*)&out[base + BH + hidx] = make_float2(c0, c1);
        }
    }
}

// ====================================================================
// launch
// ====================================================================
extern "C" void kernel_launch(void* const* d_in, const int* in_sizes, int n_in,
                              void* d_out, int out_size) {
    const float* X   = (const float*)d_in[0];
    const float* Wxi = (const float*)d_in[1];
    const float* Whi = (const float*)d_in[2];
    const float* bi  = (const float*)d_in[3];
    const float* Wxf = (const float*)d_in[4];
    const float* Whf = (const float*)d_in[5];
    const float* bf  = (const float*)d_in[6];
    const float* Wxo = (const float*)d_in[7];
    const float* Who = (const float*)d_in[8];
    const float* bo  = (const float*)d_in[9];
    const float* Wxc = (const float*)d_in[10];
    const float* Whc = (const float*)d_in[11];
    const float* bc  = (const float*)d_in[12];
    float* out = (float*)d_out;

    // Phase 0: split X / Wx into bf16 hi/lo, build bias concat
    int cblocks = (int)((NX4 + NW4) / 256);
    conv_prep<<<cblocks, 256>>>(X, Wxi, Wxf, Wxo, Wxc, bi, bf, bo, bc);

    // Phase 1: Xg = X @ Wxcat + b via tensor cores (accurate 3-pass)
    cudaFuncSetAttribute(xg_mma, cudaFuncAttributeMaxDynamicSharedMemorySize,
                         XG_SMEM);
    xg_mma<<<dim3(32, 256), 256, XG_SMEM>>>();

    // Phase 2: persistent recurrence, single-pass fp16 + resident B
    cudaFuncSetAttribute(lstm_rec, cudaFuncAttributeMaxDynamicSharedMemorySize,
                         RT6);
    lstm_rec<<<NCTA, 256, RT6>>>(Whi, Whf, Who, Whc, out, out_size);
}

// round 13
// speedup vs baseline: 1.7747x; 1.1931x over previous
#include <cuda_runtime.h>
#include <cuda_bf16.h>
#include <cuda_fp16.h>
#include <cstdint>
#include <math.h>

// ---------------- problem constants ----------------
#define T_STEPS 512
#define B_SZ    64
#define D_SZ    512
#define H_SZ    1024
#define G4      4096          // 4*H
#define BH      (B_SZ*H_SZ)   // 65536
#define NCTA    128

// ---------------- global scratch / sync state ----------------
__device__ float g_xg[(size_t)T_STEPS * B_SZ * G4];   // 512 MB, Xg = X@Wx + b
__device__ __half g_Hf[2][BH];                        // H fp16, ping-pong
__device__ __half g_Xf[(size_t)T_STEPS * B_SZ * D_SZ];   // X fp16
__device__ __half g_Wxf[(size_t)D_SZ * G4];           // Wx concat fp16
__device__ float g_bcat[G4];                          // bias concat
__device__ int      g_ready[NCTA];                    // per-CTA step counter
__device__ unsigned g_arrive = 0;
__device__ unsigned g_gen    = 0;

// ---------------- helpers ----------------
__device__ __forceinline__ uint32_t smem_u32(const void* p) {
    uint32_t a;
    asm("{ .reg .u64 t; cvta.to.shared.u64 t, %1; cvt.u32.u64 %0, t; }" : "=r"(a) : "l"(p));
    return a;
}
__device__ __forceinline__ void ldsm_x4(uint32_t* r, uint32_t addr) {
    asm volatile("ldmatrix.sync.aligned.m8n8.x4.shared.b16 {%0,%1,%2,%3}, [%4];"
                 : "=r"(r[0]), "=r"(r[1]), "=r"(r[2]), "=r"(r[3]) : "r"(addr));
}
__device__ __forceinline__ void ldsm_x4t(uint32_t* r, uint32_t addr) {
    asm volatile("ldmatrix.sync.aligned.m8n8.x4.trans.shared.b16 {%0,%1,%2,%3}, [%4];"
                 : "=r"(r[0]), "=r"(r[1]), "=r"(r[2]), "=r"(r[3]) : "r"(addr));
}
// fp16 mma
__device__ __forceinline__ void mma16816h(float* c, const uint32_t* a, uint32_t b0, uint32_t b1) {
    asm volatile(
        "mma.sync.aligned.m16n8k16.row.col.f32.f16.f16.f32 "
        "{%0,%1,%2,%3}, {%4,%5,%6,%7}, {%8,%9}, {%0,%1,%2,%3};"
        : "+f"(c[0]), "+f"(c[1]), "+f"(c[2]), "+f"(c[3])
        : "r"(a[0]), "r"(a[1]), "r"(a[2]), "r"(a[3]), "r"(b0), "r"(b1));
}
__device__ __forceinline__ void cp16(uint32_t saddr, const void* g) {
    asm volatile("cp.async.cg.shared.global [%0], [%1], 16;" :: "r"(saddr), "l"(g));
}
#define CP_COMMIT() asm volatile("cp.async.commit_group;" ::: "memory")
#define CP_WAIT(N)  asm volatile("cp.async.wait_group %0;" :: "n"(N) : "memory")

__device__ __forceinline__ void bar_named(int id, int cnt) {
    asm volatile("bar.sync %0, %1;" :: "r"(id), "r"(cnt) : "memory");
}
__device__ __forceinline__ void wait_ready(int idx, int target) {
    int v;
    do {
        asm volatile("ld.acquire.gpu.s32 %0, [%1];" : "=r"(v) : "l"(g_ready + idx) : "memory");
        if (v < target) __nanosleep(32);
    } while (v < target);
}

// self-resetting generation barrier (replay-safe)
__device__ __forceinline__ void init_barrier() {
    __syncthreads();
    if (threadIdx.x == 0) {
        __threadfence();
        unsigned gen;
        asm volatile("ld.acquire.gpu.u32 %0, [%1];" : "=r"(gen) : "l"(&g_gen) : "memory");
        unsigned old = atomicAdd(&g_arrive, 1u);
        if (old == NCTA - 1) {
            atomicExch(&g_arrive, 0u);
            __threadfence();
            atomicAdd(&g_gen, 1u);
        } else {
            unsigned cur;
            do {
                __nanosleep(64);
                asm volatile("ld.acquire.gpu.u32 %0, [%1];" : "=r"(cur) : "l"(&g_gen) : "memory");
            } while (cur == gen);
        }
        __threadfence();
    }
    __syncthreads();
}

// ====================================================================
// Kernel 0: convert X and Wx (concat) to fp16; build bias concat.
// ====================================================================
#define NX4 ((size_t)T_STEPS * B_SZ * D_SZ / 4)      // 4,194,304
#define NW4 ((size_t)D_SZ * G4 / 4)                  // 524,288

__global__ void __launch_bounds__(256) conv_prep(
    const float* __restrict__ X,
    const float* __restrict__ Wx0, const float* __restrict__ Wx1,
    const float* __restrict__ Wx2, const float* __restrict__ Wx3,
    const float* __restrict__ b0p, const float* __restrict__ b1p,
    const float* __restrict__ b2p, const float* __restrict__ b3p)
{
    size_t i = (size_t)blockIdx.x * 256 + threadIdx.x;
    if (i < NX4) {
        float4 v = ((const float4*)X)[i];
        __half h0 = __float2half_rn(v.x), h1 = __float2half_rn(v.y);
        __half h2 = __float2half_rn(v.z), h3 = __float2half_rn(v.w);
        unsigned a = (unsigned)*(unsigned short*)&h0 | ((unsigned)*(unsigned short*)&h1 << 16);
        unsigned b = (unsigned)*(unsigned short*)&h2 | ((unsigned)*(unsigned short*)&h3 << 16);
        *(uint2*)&g_Xf[i * 4] = make_uint2(a, b);
    } else if (i < NX4 + NW4) {
        size_t d = i - NX4;
        int k  = (int)(d >> 10);
        int c4 = (int)(d & 1023);
        int col  = c4 * 4;
        int gate = col >> 10;
        int n    = col & 1023;
        const float* W = (gate == 0) ? Wx0 : (gate == 1) ? Wx1 : (gate == 2) ? Wx2 : Wx3;
        float4 v = *(const float4*)&W[(size_t)k * 1024 + n];
        __half h0 = __float2half_rn(v.x), h1 = __float2half_rn(v.y);
        __half h2 = __float2half_rn(v.z), h3 = __float2half_rn(v.w);
        unsigned a = (unsigned)*(unsigned short*)&h0 | ((unsigned)*(unsigned short*)&h1 << 16);
        unsigned b = (unsigned)*(unsigned short*)&h2 | ((unsigned)*(unsigned short*)&h3 << 16);
        *(uint2*)&g_Wxf[d * 4] = make_uint2(a, b);
    }
    if (i < G4 / 4) {
        int col = (int)i * 4;
        int gate = col >> 10, n = col & 1023;
        const float* bg = (gate == 0) ? b0p : (gate == 1) ? b1p : (gate == 2) ? b2p : b3p;
        ((float4*)g_bcat)[i] = *(const float4*)&bg[n];
    }
}

// ====================================================================
// Kernel 1: Xg = X @ Wxcat + bcat, single-pass fp16 mma.sync.
// CTA tile 128(m) x 128(n), K=512 in 8 chunks of 64, cp.async double buf.
// SMEM 70KB -> 2 CTAs/SM.
// ====================================================================
#define XA(buf) ((buf)*18432)                      // [128][72] fp16
#define XB(buf) (36864 + (buf)*17408)              // [64][136] fp16
#define XG_SMEM 71680

__global__ void __launch_bounds__(256, 2) xg_mma()
{
    extern __shared__ char smc[];
    const uint32_t smem_base = smem_u32(smc);
    const int tid  = threadIdx.x;
    const int wid  = tid >> 5;
    const int lane = tid & 31;
    const int m0   = blockIdx.y * 128;
    const int nb   = blockIdx.x * 128;
    const int mw   = (wid & 3) * 32;
    const int nw   = (wid >> 2) * 64;

    const int arow = ((lane >> 3) & 1) * 8 + (lane & 7);
    const int acol = (lane >> 4) * 8;
    const int brow = ((lane >> 3) & 1) * 8 + (lane & 7);
    const int bcol = (lane >> 4) * 8;

    float acc[2][8][4];
    #pragma unroll
    for (int m = 0; m < 2; ++m)
        #pragma unroll
        for (int n = 0; n < 8; ++n)
            #pragma unroll
            for (int q = 0; q < 4; ++q) acc[m][n][q] = 0.f;

    auto issue_chunk = [&](int s, int buf) {
        #pragma unroll
        for (int i = 0; i < 4; ++i) {
            int idx = tid + i * 256;
            int row = idx >> 3, c8 = (idx & 7) * 8;
            uint32_t sa = smem_base + XA(buf) + (uint32_t)(row * 72 + c8) * 2u;
            cp16(sa, g_Xf + (size_t)(m0 + row) * D_SZ + s * 64 + c8);
        }
        #pragma unroll
        for (int i = 0; i < 4; ++i) {
            int idx = tid + i * 256;
            int r = idx >> 4, c8 = (idx & 15) * 8;
            uint32_t sb = smem_base + XB(buf) + (uint32_t)(r * 136 + c8) * 2u;
            cp16(sb, g_Wxf + (size_t)(s * 64 + r) * G4 + nb + c8);
        }
        CP_COMMIT();
    };

    issue_chunk(0, 0);
    #pragma unroll 1
    for (int s = 0; s < 8; ++s) {
        if (s < 7) { issue_chunk(s + 1, (s + 1) & 1); CP_WAIT(1); }
        else       { CP_WAIT(0); }
        __syncthreads();

        const int buf = s & 1;
        const uint32_t Ah = smem_base + XA(buf);
        const uint32_t Bh = smem_base + XB(buf);
        #pragma unroll
        for (int kt = 0; kt < 4; ++kt) {
            uint32_t ah[2][4];
            #pragma unroll
            for (int m = 0; m < 2; ++m)
                ldsm_x4(ah[m], Ah + (uint32_t)((mw + m * 16 + arow) * 72 + kt * 16 + acol) * 2u);
            uint32_t bh[4][4];
            #pragma unroll
            for (int np = 0; np < 4; ++np)
                ldsm_x4t(bh[np], Bh + (uint32_t)((kt * 16 + brow) * 136 + nw + np * 16 + bcol) * 2u);
            #pragma unroll
            for (int m = 0; m < 2; ++m)
                #pragma unroll
                for (int np = 0; np < 4; ++np) {
                    mma16816h(acc[m][2*np],   ah[m], bh[np][0], bh[np][1]);
                    mma16816h(acc[m][2*np+1], ah[m], bh[np][2], bh[np][3]);
                }
        }
        __syncthreads();
    }

    const int r0    = m0 + mw + (lane >> 2);
    const int cbase = nb + nw + (lane & 3) * 2;
    #pragma unroll
    for (int m = 0; m < 2; ++m) {
        #pragma unroll
        for (int nt = 0; nt < 8; ++nt) {
            int col = cbase + nt * 8;
            float b0 = g_bcat[col], b1 = g_bcat[col + 1];
            int rr = r0 + m * 16;
            float* p0 = g_xg + (size_t)rr * G4 + col;
            float* p1 = g_xg + (size_t)(rr + 8) * G4 + col;
            *(float2*)p0 = make_float2(acc[m][nt][0] + b0, acc[m][nt][1] + b1);
            *(float2*)p1 = make_float2(acc[m][nt][2] + b0, acc[m][nt][3] + b1);
        }
    }
}

// ====================================================================
// Kernel 2: persistent recurrence v7 — 512 threads / 16 warps.
// Warp pair (2j, 2j+1) shares K-slice j (K=128) and a 3-deep shared
// A-ring; within the pair warps split N (16 gate-cols each): B stays
// 32 regs, acc 32 regs. Each warp stages half the A rows (even: 0-31,
// odd: 32-63); pair syncs via named bar(1+j, 64). 3 ring buffers make
// stage(s+2)-after-bar(s) race-free (partner finished compute(s-1)
// before bar(s); buf (s+2)%3 == (s-1)%3). 8 partial buffers as in R12
// (pair writes disjoint columns) -> reduce/epilogue unchanged.
// ====================================================================

#define RRING 15360                   // per-pair ring: 3 bufs x 5120B
#define RG7   122880                  // partials: 8 x 64 x 33 f32 = 67584
#define RT7   190464                  // total dynamic smem

__global__ void __launch_bounds__(512, 1) lstm_rec(
    const float* __restrict__ Wh0, const float* __restrict__ Wh1,
    const float* __restrict__ Wh2, const float* __restrict__ Wh3,
    float* __restrict__ out, int out_size)
{
    extern __shared__ char smc[];
    const uint32_t smem_base = smem_u32(smc);
    const int tid  = threadIdx.x;
    const int wid  = tid >> 5;
    const int lane = tid & 31;
    const int h0   = blockIdx.x * 8;

    if (tid == 0) g_ready[blockIdx.x] = 0;

    // ---- stage W slice fp16 (stride 40 halves, temp at offset 0) ----
    {
        __half* w = (__half*)smc;
        for (int i = tid; i < 32 * 1024; i += 512) {
            int k = i >> 5, n = i & 31;
            int gate = n >> 3;
            const float* W = (gate == 0) ? Wh0 : (gate == 1) ? Wh1
                             : (gate == 2) ? Wh2 : Wh3;
            w[k * 40 + n] = __float2half_rn(W[(size_t)k * H_SZ + h0 + (n & 7)]);
        }
    }
    __syncthreads();

    // ---- extract register-resident B fragments (once) ----
    const int j     = wid >> 1;        // K-slice 0..7
    const int nhalf = wid & 1;         // N half: cols nhalf*16..+16
    const int brow  = ((lane >> 3) & 1) * 8 + (lane & 7);
    const int bcol0 = (lane >> 4) * 8;
    uint32_t bf[8][4];                 // [k-tile][reg]: 16 cols
    #pragma unroll
    for (int kt = 0; kt < 8; ++kt) {
        uint32_t off = (uint32_t)((j * 128 + kt * 16 + brow) * 40
                                  + nhalf * 16 + bcol0) * 2u;
        ldsm_x4t(bf[kt], smem_base + off);
    }
    init_barrier();   // flags reset visible; W area now reusable as rings

    // ---- ring / ldsm geometry ----
    const uint32_t ring = smem_base + (uint32_t)j * RRING;   // shared by pair
    const int arow  = ((lane >> 3) & 1) * 8 + (lane & 7);
    const uint32_t a_lane = (uint32_t)(arow * 80 + ((lane >> 4) << 4));
    const int barid = 1 + j;
    // epilogue mapping (tid < 256 only)
    const int b2 = tid >> 2;
    const int hq = (tid & 3) * 2;
    const size_t hidx = (size_t)b2 * H_SZ + h0 + hq;

    float* P  = (float*)(smc + RG7);
    float* Pw = P + j * 2112;          // pair's partial [64][33]
    const int colbase = nhalf * 16;

    float c0 = 0.f, c1 = 0.f;

    for (int t = 0; t < T_STEPS; ++t) {
        float acc[4][2][4];
        #pragma unroll
        for (int m = 0; m < 4; ++m)
            #pragma unroll
            for (int n = 0; n < 2; ++n)
                #pragma unroll
                for (int q = 0; q < 4; ++q) acc[m][n][q] = 0.f;

        // ---- Xg prefetch into registers (epilogue threads only) ----
        float2 xv0, xv1, xv2, xv3;
        if (tid < 256) {
            const float* xb = g_xg + ((size_t)t * B_SZ + b2) * G4 + h0 + hq;
            xv0 = __ldcg((const float2*)xb);
            xv1 = __ldcg((const float2*)(xb + 1024));
            xv2 = __ldcg((const float2*)(xb + 2048));
            xv3 = __ldcg((const float2*)(xb + 3072));
        }

        if (t > 0) {
            const __half* Hf = g_Hf[(t - 1) & 1];

            // stage half the rows of chunk sc into ring buf sc%3
            auto stage = [&](int sc) {
                if (lane < 4) {
                    int idx = j * 16 + sc * 4 + lane;
                    int v = __ldcg(&g_ready[idx]);
                    if (v < t) wait_ready(idx, t);
                }
                __syncwarp();
                const uint32_t dst = ring + (uint32_t)(sc % 3) * 5120u;
                const int k0 = j * 128 + sc * 32;
                #pragma unroll
                for (int q = 0; q < 4; ++q) {
                    int idx = q * 32 + lane;                 // 0..127
                    int row = nhalf * 32 + (idx >> 2);
                    int c4  = idx & 3;
                    cp16(dst + (uint32_t)(row * 80 + c4 * 16),
                         Hf + (size_t)row * H_SZ + k0 + c4 * 8);
                }
                CP_COMMIT();
            };

            stage(0); stage(1);

            #pragma unroll
            for (int sc = 0; sc < 4; ++sc) {
                if (sc < 3) CP_WAIT(1); else CP_WAIT(0);
                bar_named(barid, 64);      // partner's half staged + visible
                const uint32_t base = ring + (uint32_t)(sc % 3) * 5120u;
                #pragma unroll
                for (int ktl = 0; ktl < 2; ++ktl) {
                    const int kt = sc * 2 + ktl;
                    #pragma unroll
                    for (int mt = 0; mt < 4; ++mt) {
                        uint32_t av[4];
                        ldsm_x4(av, base + (uint32_t)(mt * 1280)
                                     + (uint32_t)(ktl * 32) + a_lane);
                        #pragma unroll
                        for (int nt = 0; nt < 2; ++nt)
                            mma16816h(acc[mt][nt], av, bf[kt][nt*2], bf[kt][nt*2+1]);
                    }
                }
                if (sc < 2) stage(sc + 2);
            }

            // store this warp's partial columns [64][colbase..colbase+16)
            #pragma unroll
            for (int mt = 0; mt < 4; ++mt) {
                int r0 = mt * 16 + (lane >> 2);
                #pragma unroll
                for (int nt = 0; nt < 2; ++nt) {
                    int col = colbase + nt * 8 + (lane & 3) * 2;
                    Pw[r0 * 33 + col]           = acc[mt][nt][0];
                    Pw[r0 * 33 + col + 1]       = acc[mt][nt][1];
                    Pw[(r0 + 8) * 33 + col]     = acc[mt][nt][2];
                    Pw[(r0 + 8) * 33 + col + 1] = acc[mt][nt][3];
                }
            }
        }

        __syncthreads();   // partials visible

        float Hn0 = 0.f, Hn1 = 0.f;
        if (tid < 256) {
            // ---- reduce 8 partials + gate math ----
            float gi0 = xv0.x, gi1 = xv0.y, gf0 = xv1.x, gf1 = xv1.y;
            float go0 = xv2.x, go1 = xv2.y, gc0 = xv3.x, gc1 = xv3.y;
            if (t > 0) {
                #pragma unroll
                for (int w = 0; w < 8; ++w) {
                    const float* pr = P + w * 2112 + b2 * 33;
                    gi0 += pr[hq];      gi1 += pr[hq + 1];
                    gf0 += pr[8 + hq];  gf1 += pr[8 + hq + 1];
                    go0 += pr[16 + hq]; go1 += pr[16 + hq + 1];
                    gc0 += pr[24 + hq]; gc1 += pr[24 + hq + 1];
                }
            }

            float Iv = __fdividef(1.f, 1.f + __expf(-gi0));
            float Fv = __fdividef(1.f, 1.f + __expf(-gf0));
            float Ov = __fdividef(1.f, 1.f + __expf(-go0));
            float Ct = 1.f - __fdividef(2.f, __expf(2.f * gc0) + 1.f);
            c0 = Fv * c0 + Iv * Ct;
            Hn0 = Ov * (1.f - __fdividef(2.f, __expf(2.f * c0) + 1.f));

            Iv = __fdividef(1.f, 1.f + __expf(-gi1));
            Fv = __fdividef(1.f, 1.f + __expf(-gf1));
            Ov = __fdividef(1.f, 1.f + __expf(-go1));
            Ct = 1.f - __fdividef(2.f, __expf(2.f * gc1) + 1.f);
            c1 = Fv * c1 + Iv * Ct;
            Hn1 = Ov * (1.f - __fdividef(2.f, __expf(2.f * c1) + 1.f));

            // publish fp16 H
            const int wb = t & 1;
            __half h0h = __float2half_rn(Hn0);
            __half h1h = __float2half_rn(Hn1);
            unsigned hp = (unsigned)*(unsigned short*)&h0h
                        | ((unsigned)*(unsigned short*)&h1h << 16);
            *(unsigned*)&g_Hf[wb][hidx] = hp;
            __threadfence();   // release H writes
        }
        __syncthreads();       // all H published
        if (tid == 0) atomicAdd(&g_ready[blockIdx.x], 1);

        // fp32 outputs after the flag (off the recurrence critical path)
        if (tid < 256) {
            *(float2*)&out[(size_t)t * BH + hidx] = make_float2(Hn0, Hn1);
            if (t == T_STEPS - 1) {
                size_t base = (size_t)T_STEPS * BH;
                if ((size_t)out_size >= base + (size_t)BH)
                    *(float2*)&out[base + hidx] = make_float2(Hn0, Hn1);
                if ((size_t)out_size >= base + 2 * (size_t)BH)
                    *(float2*)&out[base + BH + hidx] = make_float2(c0, c1);
            }
        }
    }
}

// ====================================================================
// launch
// ====================================================================
extern "C" void kernel_launch(void* const* d_in, const int* in_sizes, int n_in,
                              void* d_out, int out_size) {
    const float* X   = (const float*)d_in[0];
    const float* Wxi = (const float*)d_in[1];
    const float* Whi = (const float*)d_in[2];
    const float* bi  = (const float*)d_in[3];
    const float* Wxf = (const float*)d_in[4];
    const float* Whf = (const float*)d_in[5];
    const float* bf  = (const float*)d_in[6];
    const float* Wxo = (const float*)d_in[7];
    const float* Who = (const float*)d_in[8];
    const float* bo  = (const float*)d_in[9];
    const float* Wxc = (const float*)d_in[10];
    const float* Whc = (const float*)d_in[11];
    const float* bc  = (const float*)d_in[12];
    float* out = (float*)d_out;

    // Phase 0: convert X / Wx to fp16, build bias concat
    int cblocks = (int)((NX4 + NW4) / 256);
    conv_prep<<<cblocks, 256>>>(X, Wxi, Wxf, Wxo, Wxc, bi, bf, bo, bc);

    // Phase 1: Xg = X @ Wxcat + b, single-pass fp16 (2 CTAs/SM)
    cudaFuncSetAttribute(xg_mma, cudaFuncAttributeMaxDynamicSharedMemorySize,
                         XG_SMEM);
    xg_mma<<<dim3(32, 256), 256, XG_SMEM>>>();

    // Phase 2: persistent recurrence, 16 warps, paired K-slices
    cudaFuncSetAttribute(lstm_rec, cudaFuncAttributeMaxDynamicSharedMemorySize,
                         RT7);
    lstm_rec<<<NCTA, 512, RT7>>>(Whi, Whf, Who, Whc, out, out_size);
}